// round 16
// baseline (speedup 1.0000x reference)
#include <cuda_runtime.h>
#include <cuda_bf16.h>
#include <mma.h>
#include <math.h>
#include <stdint.h>

using namespace nvcuda;

#define S_    2048
#define HID_  2048
#define H_    16
#define D_    256
#define NOPE_ 192
#define RH_   32
#define QL_   1024
#define OR_   512
#define G_    4
#define EPS_  1e-6f
#define SCALE_ 0.0625f

// -------- fp32 scratch --------
__device__ float g_qa[S_ * QL_];
__device__ float g_q[(size_t)S_ * H_ * D_];
__device__ float g_kv[S_ * D_];
__device__ float g_or[S_ * G_ * OR_];

// -------- bf16 hi/lo scratch --------
__device__ __nv_bfloat16 g_xh[S_ * HID_],        g_xl[S_ * HID_];
__device__ __nv_bfloat16 g_wqah[QL_ * HID_],     g_wqal[QL_ * HID_];
__device__ __nv_bfloat16 g_wqbh[H_ * D_ * QL_],  g_wqbl[H_ * D_ * QL_];
__device__ __nv_bfloat16 g_qah[S_ * QL_],        g_qal[S_ * QL_];
__device__ __nv_bfloat16 g_wkvh[D_ * HID_],      g_wkvl[D_ * HID_];
__device__ __nv_bfloat16 g_woah[G_ * OR_ * 1024], g_woal[G_ * OR_ * 1024];
__device__ __nv_bfloat16 g_wobh[HID_ * G_ * OR_], g_wobl[HID_ * G_ * OR_];
__device__ __nv_bfloat16 g_oh[(size_t)S_ * H_ * D_], g_ol[(size_t)S_ * H_ * D_];
__device__ __nv_bfloat16 g_orh[S_ * G_ * OR_],   g_orl[S_ * G_ * OR_];
// attention bf16 operands
__device__ __nv_bfloat16 g_qh[(size_t)S_ * H_ * D_], g_ql2[(size_t)S_ * H_ * D_];
__device__ __nv_bfloat16 g_kvh[S_ * D_],         g_kvl[S_ * D_];

__device__ __forceinline__ uint32_t b2u(__nv_bfloat162 h) {
    return *reinterpret_cast<uint32_t*>(&h);
}
__device__ __forceinline__ void cp16(void* smem_dst, const void* gsrc) {
    uint32_t s = (uint32_t)__cvta_generic_to_shared(smem_dst);
    asm volatile("cp.async.cg.shared.global [%0], [%1], 16;" :: "r"(s), "l"(gsrc) : "memory");
}
#define CP_COMMIT() asm volatile("cp.async.commit_group;" ::: "memory")
#define CP_WAIT0()  asm volatile("cp.async.wait_group 0;" ::: "memory")
#define CP_WAIT1()  asm volatile("cp.async.wait_group 1;" ::: "memory")

// ==================== fp32 -> (hi, lo) bf16 conversion ====================
__global__ void cvt_hilo(const float* __restrict__ in,
                         __nv_bfloat16* __restrict__ h,
                         __nv_bfloat16* __restrict__ l, int n4)
{
    int i = blockIdx.x * blockDim.x + threadIdx.x;
    if (i >= n4) return;
    float4 v = ((const float4*)in)[i];
    __nv_bfloat162 h01 = __floats2bfloat162_rn(v.x, v.y);
    __nv_bfloat162 h23 = __floats2bfloat162_rn(v.z, v.w);
    __nv_bfloat162 l01 = __floats2bfloat162_rn(
        v.x - __bfloat162float(__low2bfloat16(h01)),
        v.y - __bfloat162float(__high2bfloat16(h01)));
    __nv_bfloat162 l23 = __floats2bfloat162_rn(
        v.z - __bfloat162float(__low2bfloat16(h23)),
        v.w - __bfloat162float(__high2bfloat16(h23)));
    ((uint2*)h)[i] = make_uint2(b2u(h01), b2u(h23));
    ((uint2*)l)[i] = make_uint2(b2u(l01), b2u(l23));
}

// ==================== split-bf16 tensor GEMM, cp.async double-buffered ====================
#define BST 72
#define GBUF (4 * 128 * BST)              // bf16 elems per k-chunk buffer
#define GBF_SMEM (2 * GBUF * 2)           // bytes (two buffers)

__global__ void __launch_bounds__(256) gemm_bfs(
    const __nv_bfloat16* __restrict__ Ah, const __nv_bfloat16* __restrict__ Al, int lda,
    const __nv_bfloat16* __restrict__ Bh, const __nv_bfloat16* __restrict__ Bl, int ldb,
    float* __restrict__ C, int ldc, int K,
    long sAz, long sBz, long sCz)
{
    extern __shared__ __nv_bfloat16 sb[];

    Ah += (size_t)blockIdx.z * sAz;  Al += (size_t)blockIdx.z * sAz;
    Bh += (size_t)blockIdx.z * sBz;  Bl += (size_t)blockIdx.z * sBz;
    C  += (size_t)blockIdx.z * sCz;

    const int tid = threadIdx.x;
    const int warp = tid >> 5;
    const int wm = warp & 1, wn = warp >> 1;

    wmma::fragment<wmma::accumulator, 16, 16, 16, float> acc[4][2];
    #pragma unroll
    for (int i = 0; i < 4; i++)
        #pragma unroll
        for (int j = 0; j < 2; j++)
            wmma::fill_fragment(acc[i][j], 0.0f);

    const int r  = tid >> 1;
    const int c0 = (tid & 1) * 32;
    const size_t aoff = (size_t)(blockIdx.x * 128 + r) * lda + c0;
    const size_t boff = (size_t)(blockIdx.y * 128 + r) * ldb + c0;
    const int sidx = r * BST + c0;
    const int nkc = K >> 6;

    // prefetch chunk 0 into buffer 0
    {
        __nv_bfloat16* base = sb;
        #pragma unroll
        for (int j = 0; j < 4; j++) {
            cp16(base + sidx + j * 8,                 Ah + aoff + j * 8);
            cp16(base + 128 * BST + sidx + j * 8,     Al + aoff + j * 8);
            cp16(base + 2 * 128 * BST + sidx + j * 8, Bh + boff + j * 8);
            cp16(base + 3 * 128 * BST + sidx + j * 8, Bl + boff + j * 8);
        }
        CP_COMMIT();
    }

    for (int kc = 0; kc < nkc; kc++) {
        const int cur = kc & 1;
        // prefetch next chunk into alternate buffer
        if (kc + 1 < nkc) {
            __nv_bfloat16* base = sb + (cur ^ 1) * GBUF;
            const size_t ka = aoff + (size_t)(kc + 1) * 64;
            const size_t kb = boff + (size_t)(kc + 1) * 64;
            #pragma unroll
            for (int j = 0; j < 4; j++) {
                cp16(base + sidx + j * 8,                 Ah + ka + j * 8);
                cp16(base + 128 * BST + sidx + j * 8,     Al + ka + j * 8);
                cp16(base + 2 * 128 * BST + sidx + j * 8, Bh + kb + j * 8);
                cp16(base + 3 * 128 * BST + sidx + j * 8, Bl + kb + j * 8);
            }
            CP_COMMIT();
            CP_WAIT1();   // current chunk landed; newest still in flight
        } else {
            CP_WAIT0();
        }
        __syncthreads();

        __nv_bfloat16* Ah_s = sb + cur * GBUF;
        __nv_bfloat16* Al_s = Ah_s + 128 * BST;
        __nv_bfloat16* Bh_s = Ah_s + 2 * 128 * BST;
        __nv_bfloat16* Bl_s = Ah_s + 3 * 128 * BST;

        #pragma unroll
        for (int ks = 0; ks < 4; ks++) {
            wmma::fragment<wmma::matrix_a, 16, 16, 16, __nv_bfloat16, wmma::row_major> ah[4];
            wmma::fragment<wmma::matrix_b, 16, 16, 16, __nv_bfloat16, wmma::col_major> bh[2];
            #pragma unroll
            for (int i = 0; i < 4; i++)
                wmma::load_matrix_sync(ah[i], Ah_s + (wm * 64 + i * 16) * BST + ks * 16, BST);
            #pragma unroll
            for (int j = 0; j < 2; j++)
                wmma::load_matrix_sync(bh[j], Bh_s + (wn * 32 + j * 16) * BST + ks * 16, BST);
            #pragma unroll
            for (int i = 0; i < 4; i++)
                #pragma unroll
                for (int j = 0; j < 2; j++)
                    wmma::mma_sync(acc[i][j], ah[i], bh[j], acc[i][j]);
            {
                wmma::fragment<wmma::matrix_b, 16, 16, 16, __nv_bfloat16, wmma::col_major> bl[2];
                #pragma unroll
                for (int j = 0; j < 2; j++)
                    wmma::load_matrix_sync(bl[j], Bl_s + (wn * 32 + j * 16) * BST + ks * 16, BST);
                #pragma unroll
                for (int i = 0; i < 4; i++)
                    #pragma unroll
                    for (int j = 0; j < 2; j++)
                        wmma::mma_sync(acc[i][j], ah[i], bl[j], acc[i][j]);
            }
            {
                wmma::fragment<wmma::matrix_a, 16, 16, 16, __nv_bfloat16, wmma::row_major> al[4];
                #pragma unroll
                for (int i = 0; i < 4; i++)
                    wmma::load_matrix_sync(al[i], Al_s + (wm * 64 + i * 16) * BST + ks * 16, BST);
                #pragma unroll
                for (int i = 0; i < 4; i++)
                    #pragma unroll
                    for (int j = 0; j < 2; j++)
                        wmma::mma_sync(acc[i][j], al[i], bh[j], acc[i][j]);
            }
        }
        __syncthreads();   // all reads of buf cur done before it is refilled
    }

    #pragma unroll
    for (int i = 0; i < 4; i++)
        #pragma unroll
        for (int j = 0; j < 2; j++) {
            float* Cp = C + (size_t)(blockIdx.x * 128 + wm * 64 + i * 16) * ldc
                          + blockIdx.y * 128 + wn * 32 + j * 16;
            wmma::store_matrix_sync(Cp, acc[i][j], ldc, wmma::mem_row_major);
        }
}

// ==================== RMS norm (L=1024) emitting hi/lo bf16 ====================
__global__ void rmsnorm_hilo(const float* __restrict__ x, const float* __restrict__ w,
                             __nv_bfloat16* __restrict__ h, __nv_bfloat16* __restrict__ l)
{
    int row = blockIdx.x;
    int t = threadIdx.x;
    const float4* p = (const float4*)(x + (size_t)row * QL_);
    float4 v = p[t];
    float ss = v.x * v.x + v.y * v.y + v.z * v.z + v.w * v.w;
    __shared__ float red[8];
    #pragma unroll
    for (int o = 16; o; o >>= 1) ss += __shfl_xor_sync(0xffffffffu, ss, o);
    if ((t & 31) == 0) red[t >> 5] = ss;
    __syncthreads();
    if (t < 32) {
        float r = (t < 8) ? red[t] : 0.f;
        #pragma unroll
        for (int o = 4; o; o >>= 1) r += __shfl_xor_sync(0xffffffffu, r, o);
        if (t == 0) red[0] = r;
    }
    __syncthreads();
    float inv = rsqrtf(red[0] / (float)QL_ + EPS_);
    float4 wv = ((const float4*)w)[t];
    float4 o4 = make_float4(v.x * inv * wv.x, v.y * inv * wv.y,
                            v.z * inv * wv.z, v.w * inv * wv.w);
    __nv_bfloat162 h01 = __floats2bfloat162_rn(o4.x, o4.y);
    __nv_bfloat162 h23 = __floats2bfloat162_rn(o4.z, o4.w);
    __nv_bfloat162 l01 = __floats2bfloat162_rn(
        o4.x - __bfloat162float(__low2bfloat16(h01)),
        o4.y - __bfloat162float(__high2bfloat16(h01)));
    __nv_bfloat162 l23 = __floats2bfloat162_rn(
        o4.z - __bfloat162float(__low2bfloat16(h23)),
        o4.w - __bfloat162float(__high2bfloat16(h23)));
    ((uint2*)(h + (size_t)row * QL_))[t] = make_uint2(b2u(h01), b2u(h23));
    ((uint2*)(l + (size_t)row * QL_))[t] = make_uint2(b2u(l01), b2u(l23));
}

// ==================== q prep: warp-per-row ====================
__global__ void qprep(const float* __restrict__ q, const float* __restrict__ freqs,
                      __nv_bfloat16* __restrict__ qh, __nv_bfloat16* __restrict__ ql)
{
    int row = blockIdx.x * 8 + (threadIdx.x >> 5);
    int lane = threadIdx.x & 31;
    const float* p = q + (size_t)row * D_ + lane * 8;
    float4 a = *(const float4*)p;
    float4 b = *(const float4*)(p + 4);
    float ss = a.x*a.x + a.y*a.y + a.z*a.z + a.w*a.w
             + b.x*b.x + b.y*b.y + b.z*b.z + b.w*b.w;
    #pragma unroll
    for (int o = 16; o; o >>= 1) ss += __shfl_xor_sync(0xffffffffu, ss, o);
    float inv = rsqrtf(ss / (float)D_ + EPS_) * SCALE_;
    float v[8] = {a.x*inv, a.y*inv, a.z*inv, a.w*inv,
                  b.x*inv, b.y*inv, b.z*inv, b.w*inv};
    int col0 = lane * 8;
    if (col0 >= NOPE_) {
        int s = row >> 4;
        #pragma unroll
        for (int j = 0; j < 8; j += 2) {
            int i = (col0 + j - NOPE_) >> 1;
            float f = freqs[s * RH_ + i];
            float c = cosf(f), sn = sinf(f);
            float x1 = v[j], x2 = v[j + 1];
            v[j]     = x1 * c - x2 * sn;
            v[j + 1] = x1 * sn + x2 * c;
        }
    }
    uint32_t hh[4], ll[4];
    #pragma unroll
    for (int j = 0; j < 4; j++) {
        __nv_bfloat162 hi = __floats2bfloat162_rn(v[2*j], v[2*j+1]);
        __nv_bfloat162 lo = __floats2bfloat162_rn(
            v[2*j]   - __bfloat162float(__low2bfloat16(hi)),
            v[2*j+1] - __bfloat162float(__high2bfloat16(hi)));
        hh[j] = b2u(hi); ll[j] = b2u(lo);
    }
    size_t idx = (size_t)row * D_ + col0;
    *(uint4*)(qh + idx) = make_uint4(hh[0], hh[1], hh[2], hh[3]);
    *(uint4*)(ql + idx) = make_uint4(ll[0], ll[1], ll[2], ll[3]);
}

// ==================== kv prep: warp-per-row ====================
__global__ void kvprep(const float* __restrict__ kv, const float* __restrict__ w,
                       const float* __restrict__ freqs,
                       __nv_bfloat16* __restrict__ kvh, __nv_bfloat16* __restrict__ kvl)
{
    int s = blockIdx.x * 8 + (threadIdx.x >> 5);
    int lane = threadIdx.x & 31;
    const float* p = kv + (size_t)s * D_ + lane * 8;
    float4 a = *(const float4*)p;
    float4 b = *(const float4*)(p + 4);
    float ss = a.x*a.x + a.y*a.y + a.z*a.z + a.w*a.w
             + b.x*b.x + b.y*b.y + b.z*b.z + b.w*b.w;
    #pragma unroll
    for (int o = 16; o; o >>= 1) ss += __shfl_xor_sync(0xffffffffu, ss, o);
    float inv = rsqrtf(ss / (float)D_ + EPS_);
    float4 w0 = *(const float4*)(w + lane * 8);
    float4 w1 = *(const float4*)(w + lane * 8 + 4);
    float v[8] = {a.x*inv*w0.x, a.y*inv*w0.y, a.z*inv*w0.z, a.w*inv*w0.w,
                  b.x*inv*w1.x, b.y*inv*w1.y, b.z*inv*w1.z, b.w*inv*w1.w};
    int col0 = lane * 8;
    if (col0 >= NOPE_) {
        #pragma unroll
        for (int j = 0; j < 8; j += 2) {
            int i = (col0 + j - NOPE_) >> 1;
            float f = freqs[s * RH_ + i];
            float c = cosf(f), sn = sinf(f);
            float x1 = v[j], x2 = v[j + 1];
            v[j]     = x1 * c - x2 * sn;
            v[j + 1] = x1 * sn + x2 * c;
        }
    }
    uint32_t hh[4], ll[4];
    #pragma unroll
    for (int j = 0; j < 4; j++) {
        __nv_bfloat162 hi = __floats2bfloat162_rn(v[2*j], v[2*j+1]);
        __nv_bfloat162 lo = __floats2bfloat162_rn(
            v[2*j]   - __bfloat162float(__low2bfloat16(hi)),
            v[2*j+1] - __bfloat162float(__high2bfloat16(hi)));
        hh[j] = b2u(hi); ll[j] = b2u(lo);
    }
    size_t idx = (size_t)s * D_ + col0;
    *(uint4*)(kvh + idx) = make_uint4(hh[0], hh[1], hh[2], hh[3]);
    *(uint4*)(kvl + idx) = make_uint4(ll[0], ll[1], ll[2], ll[3]);
}

// ==================== WMMA flash attention, 64q x 64k, KV double-buffered (cp.async) ========
#define AQS 264
#define APS 72
#define PVS 260
#define ATT_SMEM (2*64*AQS*2 + 4*64*AQS*2 + 64*APS*4 + 64*4)

__global__ void __launch_bounds__(256) attn_wmma(
    const __nv_bfloat16* __restrict__ qh, const __nv_bfloat16* __restrict__ ql,
    const __nv_bfloat16* __restrict__ kvh, const __nv_bfloat16* __restrict__ kvl,
    const float* __restrict__ sink, const float* __restrict__ freqs,
    __nv_bfloat16* __restrict__ ohi, __nv_bfloat16* __restrict__ olo)
{
    extern __shared__ char sm8[];
    __nv_bfloat16* Qh  = (__nv_bfloat16*)sm8;
    __nv_bfloat16* Ql  = Qh + 64 * AQS;
    __nv_bfloat16* KVbase = Ql + 64 * AQS;
    float* Sf = (float*)(KVbase + 4 * 64 * AQS);
    __nv_bfloat16* Ph = (__nv_bfloat16*)Sf;
    __nv_bfloat16* Pl = Ph + 64 * APS;
    float* rowl = Sf + 64 * APS;
    float* PVb = (float*)Qh;

    const int qb = (int)(gridDim.x - 1 - blockIdx.x);
    const int h  = blockIdx.y;
    const int s0 = qb * 64;
    const int tid = threadIdx.x;
    const int warp = tid >> 5;

    const int kr = tid >> 2, kc0 = (tid & 3) * 64;

    {
        __nv_bfloat16* KVh0 = KVbase;
        __nv_bfloat16* KVl0 = KVbase + 64 * AQS;
        const __nv_bfloat16* gh = kvh + (size_t)kr * D_ + kc0;
        const __nv_bfloat16* gl = kvl + (size_t)kr * D_ + kc0;
        #pragma unroll
        for (int j = 0; j < 8; j++) {
            cp16(KVh0 + kr * AQS + kc0 + j * 8, gh + j * 8);
            cp16(KVl0 + kr * AQS + kc0 + j * 8, gl + j * 8);
        }
        CP_COMMIT();
    }

    {
        int r = tid >> 2, c0 = (tid & 3) * 64;
        const uint4* gh = (const uint4*)(qh + ((size_t)(s0 + r) * H_ + h) * D_ + c0);
        const uint4* gl = (const uint4*)(ql + ((size_t)(s0 + r) * H_ + h) * D_ + c0);
        #pragma unroll
        for (int j = 0; j < 8; j++) {
            *(uint4*)(Qh + r * AQS + c0 + j * 8) = gh[j];
            *(uint4*)(Ql + r * AQS + c0 + j * 8) = gl[j];
        }
    }
    if (tid < 64) rowl[tid] = 0.f;

    const int wS_m = warp & 3, wS_n = warp >> 2;
    const int wP_m = warp & 1, wP_n = warp >> 1;

    wmma::fragment<wmma::accumulator, 16, 16, 16, float> pacc[2][4];
    #pragma unroll
    for (int i = 0; i < 2; i++)
        #pragma unroll
        for (int n = 0; n < 4; n++) wmma::fill_fragment(pacc[i][n], 0.0f);

    CP_WAIT0();
    __syncthreads();

    const int ntiles = qb + 1;
    for (int t0 = 0; t0 < ntiles; t0++) {
        const int cur = t0 & 1;
        __nv_bfloat16* KVh = KVbase + cur * (2 * 64 * AQS);
        __nv_bfloat16* KVl = KVh + 64 * AQS;

        if (t0 + 1 < ntiles) {
            __nv_bfloat16* KVhN = KVbase + (cur ^ 1) * (2 * 64 * AQS);
            __nv_bfloat16* KVlN = KVhN + 64 * AQS;
            const __nv_bfloat16* gh = kvh + (size_t)((t0 + 1) * 64 + kr) * D_ + kc0;
            const __nv_bfloat16* gl = kvl + (size_t)((t0 + 1) * 64 + kr) * D_ + kc0;
            #pragma unroll
            for (int j = 0; j < 8; j++) {
                cp16(KVhN + kr * AQS + kc0 + j * 8, gh + j * 8);
                cp16(KVlN + kr * AQS + kc0 + j * 8, gl + j * 8);
            }
            CP_COMMIT();
        }

        {
            wmma::fragment<wmma::accumulator, 16, 16, 16, float> sacc[2];
            #pragma unroll
            for (int j = 0; j < 2; j++) wmma::fill_fragment(sacc[j], 0.0f);
            #pragma unroll 2
            for (int ks = 0; ks < 16; ks++) {
                wmma::fragment<wmma::matrix_a, 16, 16, 16, __nv_bfloat16, wmma::row_major> ah, al;
                wmma::fragment<wmma::matrix_b, 16, 16, 16, __nv_bfloat16, wmma::col_major> bh[2], bl[2];
                wmma::load_matrix_sync(ah, Qh + (wS_m * 16) * AQS + ks * 16, AQS);
                wmma::load_matrix_sync(al, Ql + (wS_m * 16) * AQS + ks * 16, AQS);
                #pragma unroll
                for (int j = 0; j < 2; j++) {
                    wmma::load_matrix_sync(bh[j], KVh + (wS_n * 32 + j * 16) * AQS + ks * 16, AQS);
                    wmma::load_matrix_sync(bl[j], KVl + (wS_n * 32 + j * 16) * AQS + ks * 16, AQS);
                }
                #pragma unroll
                for (int j = 0; j < 2; j++) {
                    wmma::mma_sync(sacc[j], ah, bh[j], sacc[j]);
                    wmma::mma_sync(sacc[j], ah, bl[j], sacc[j]);
                    wmma::mma_sync(sacc[j], al, bh[j], sacc[j]);
                }
            }
            #pragma unroll
            for (int j = 0; j < 2; j++)
                wmma::store_matrix_sync(Sf + (wS_m * 16) * APS + wS_n * 32 + j * 16,
                                        sacc[j], APS, wmma::mem_row_major);
        }
        __syncthreads();

        {
            int r = tid >> 2, sub = tid & 3;
            float e[16];
            float psum = 0.f;
            #pragma unroll
            for (int tt = 0; tt < 16; tt++) {
                int c = sub * 16 + tt;
                float v = Sf[r * APS + c];
                e[tt] = (t0 * 64 + c <= s0 + r) ? __expf(v) : 0.f;
                psum += e[tt];
            }
            psum += __shfl_xor_sync(0xffffffffu, psum, 1);
            psum += __shfl_xor_sync(0xffffffffu, psum, 2);
            if (sub == 0) rowl[r] += psum;
            __syncthreads();
            #pragma unroll
            for (int tt = 0; tt < 16; tt++) {
                int c = sub * 16 + tt;
                __nv_bfloat16 hi = __float2bfloat16(e[tt]);
                Ph[r * APS + c] = hi;
                Pl[r * APS + c] = __float2bfloat16(e[tt] - __bfloat162float(hi));
            }
        }
        __syncthreads();

        #pragma unroll
        for (int ks = 0; ks < 4; ks++) {
            wmma::fragment<wmma::matrix_a, 16, 16, 16, __nv_bfloat16, wmma::row_major> ph[2], pl[2];
            #pragma unroll
            for (int i = 0; i < 2; i++) {
                wmma::load_matrix_sync(ph[i], Ph + (wP_m * 32 + i * 16) * APS + ks * 16, APS);
                wmma::load_matrix_sync(pl[i], Pl + (wP_m * 32 + i * 16) * APS + ks * 16, APS);
            }
            #pragma unroll
            for (int n = 0; n < 4; n++) {
                wmma::fragment<wmma::matrix_b, 16, 16, 16, __nv_bfloat16, wmma::row_major> bh, bl;
                wmma::load_matrix_sync(bh, KVh + (ks * 16) * AQS + wP_n * 64 + n * 16, AQS);
                wmma::load_matrix_sync(bl, KVl + (ks * 16) * AQS + wP_n * 64 + n * 16, AQS);
                #pragma unroll
                for (int i = 0; i < 2; i++) {
                    wmma::mma_sync(pacc[i][n], ph[i], bh, pacc[i][n]);
                    wmma::mma_sync(pacc[i][n], ph[i], bl, pacc[i][n]);
                    wmma::mma_sync(pacc[i][n], pl[i], bh, pacc[i][n]);
                }
            }
        }
        CP_WAIT0();
        __syncthreads();
    }

    #pragma unroll
    for (int i = 0; i < 2; i++)
        #pragma unroll
        for (int n = 0; n < 4; n++)
            wmma::store_matrix_sync(PVb + (wP_m * 32 + i * 16) * PVS + wP_n * 64 + n * 16,
                                    pacc[i][n], PVS, wmma::mem_row_major);
    __syncthreads();

    const int ty = tid >> 4, tx = tid & 15;
    float sk = __expf(sink[h]);
    #pragma unroll
    for (int i = 0; i < 4; i++) {
        int r = ty * 4 + i;
        int s = s0 + r;
        float inv = 1.f / (rowl[r] + sk);
        #pragma unroll
        for (int g = 0; g < 4; g++) {
            float4 pv = *(const float4*)&PVb[r * PVS + tx * 4 + g * 64];
            float4 v = make_float4(pv.x * inv, pv.y * inv, pv.z * inv, pv.w * inv);
            if (g == 3) {
                float f0 = freqs[s * RH_ + tx * 2];
                float f1 = freqs[s * RH_ + tx * 2 + 1];
                float c0 = cosf(f0), sn0 = sinf(f0);
                float c1 = cosf(f1), sn1 = sinf(f1);
                float x1 = v.x, x2 = v.y;
                v.x = x1 * c0 + x2 * sn0;
                v.y = x2 * c0 - x1 * sn0;
                float y1 = v.z, y2 = v.w;
                v.z = y1 * c1 + y2 * sn1;
                v.w = y2 * c1 - y1 * sn1;
            }
            __nv_bfloat162 h01 = __floats2bfloat162_rn(v.x, v.y);
            __nv_bfloat162 h23 = __floats2bfloat162_rn(v.z, v.w);
            __nv_bfloat162 l01 = __floats2bfloat162_rn(
                v.x - __bfloat162float(__low2bfloat16(h01)),
                v.y - __bfloat162float(__high2bfloat16(h01)));
            __nv_bfloat162 l23 = __floats2bfloat162_rn(
                v.z - __bfloat162float(__low2bfloat16(h23)),
                v.w - __bfloat162float(__high2bfloat16(h23)));
            size_t oidx = ((size_t)s * H_ + h) * D_ + tx * 4 + g * 64;
            *(uint2*)(ohi + oidx) = make_uint2(b2u(h01), b2u(h23));
            *(uint2*)(olo + oidx) = make_uint2(b2u(l01), b2u(l23));
        }
    }
}

// ==================== launch ====================
extern "C" void kernel_launch(void* const* d_in, const int* in_sizes, int n_in,
                              void* d_out, int out_size)
{
    const float* x         = (const float*)d_in[0];
    const float* freqs     = (const float*)d_in[1];
    const float* wq_a      = (const float*)d_in[2];
    const float* q_norm_w  = (const float*)d_in[3];
    const float* wq_b      = (const float*)d_in[4];
    const float* wkv       = (const float*)d_in[5];
    const float* kv_norm_w = (const float*)d_in[6];
    const float* wo_a_w    = (const float*)d_in[7];
    const float* wo_b      = (const float*)d_in[8];
    const float* attn_sink = (const float*)d_in[9];
    float* out = (float*)d_out;

    float *qa, *qbuf, *kvbuf, *orbuf;
    cudaGetSymbolAddress((void**)&qa,    g_qa);
    cudaGetSymbolAddress((void**)&qbuf,  g_q);
    cudaGetSymbolAddress((void**)&kvbuf, g_kv);
    cudaGetSymbolAddress((void**)&orbuf, g_or);

    __nv_bfloat16 *xh, *xl, *wqah, *wqal, *wqbh, *wqbl, *qah, *qal;
    __nv_bfloat16 *wkvh, *wkvl, *woah, *woal, *wobh, *wobl, *oh, *ol, *orh, *orl;
    __nv_bfloat16 *qhh, *qll, *kvh, *kvl;
    cudaGetSymbolAddress((void**)&xh, g_xh);     cudaGetSymbolAddress((void**)&xl, g_xl);
    cudaGetSymbolAddress((void**)&wqah, g_wqah); cudaGetSymbolAddress((void**)&wqal, g_wqal);
    cudaGetSymbolAddress((void**)&wqbh, g_wqbh); cudaGetSymbolAddress((void**)&wqbl, g_wqbl);
    cudaGetSymbolAddress((void**)&qah, g_qah);   cudaGetSymbolAddress((void**)&qal, g_qal);
    cudaGetSymbolAddress((void**)&wkvh, g_wkvh); cudaGetSymbolAddress((void**)&wkvl, g_wkvl);
    cudaGetSymbolAddress((void**)&woah, g_woah); cudaGetSymbolAddress((void**)&woal, g_woal);
    cudaGetSymbolAddress((void**)&wobh, g_wobh); cudaGetSymbolAddress((void**)&wobl, g_wobl);
    cudaGetSymbolAddress((void**)&oh, g_oh);     cudaGetSymbolAddress((void**)&ol, g_ol);
    cudaGetSymbolAddress((void**)&orh, g_orh);   cudaGetSymbolAddress((void**)&orl, g_orl);
    cudaGetSymbolAddress((void**)&qhh, g_qh);    cudaGetSymbolAddress((void**)&qll, g_ql2);
    cudaGetSymbolAddress((void**)&kvh, g_kvh);   cudaGetSymbolAddress((void**)&kvl, g_kvl);

    static int smem_set = 0;
    if (!smem_set) {
        cudaFuncSetAttribute(attn_wmma, cudaFuncAttributeMaxDynamicSharedMemorySize,
                             ATT_SMEM);
        cudaFuncSetAttribute(gemm_bfs, cudaFuncAttributeMaxDynamicSharedMemorySize,
                             GBF_SMEM);
        smem_set = 1;
    }

    dim3 blk(256);
    // ---- conversions (inputs + weights) ----
    cvt_hilo<<<(S_*HID_/4 + 255)/256, 256>>>(x,      xh,   xl,   S_*HID_/4);
    cvt_hilo<<<(QL_*HID_/4 + 255)/256, 256>>>(wq_a,  wqah, wqal, QL_*HID_/4);
    cvt_hilo<<<(H_*D_*QL_/4 + 255)/256, 256>>>(wq_b, wqbh, wqbl, H_*D_*QL_/4);
    cvt_hilo<<<(D_*HID_/4 + 255)/256, 256>>>(wkv,    wkvh, wkvl, D_*HID_/4);
    cvt_hilo<<<(G_*OR_*1024/4 + 255)/256, 256>>>(wo_a_w, woah, woal, G_*OR_*1024/4);
    cvt_hilo<<<(HID_*G_*OR_/4 + 255)/256, 256>>>(wo_b, wobh, wobl, HID_*G_*OR_/4);

    // q_a = x @ wq_a^T   [2048,1024], K=2048
    gemm_bfs<<<dim3(16, 8, 1), blk, GBF_SMEM>>>(xh, xl, HID_, wqah, wqal, HID_,
                                                qa, QL_, HID_, 0, 0, 0);
    // kv_raw = x @ wkv^T [2048,256], K=2048 (tensor path now)
    gemm_bfs<<<dim3(16, 2, 1), blk, GBF_SMEM>>>(xh, xl, HID_, wkvh, wkvl, HID_,
                                                kvbuf, D_, HID_, 0, 0, 0);
    // rms(q_a) -> hi/lo
    rmsnorm_hilo<<<S_, 256>>>(qa, q_norm_w, qah, qal);
    // q = q_a @ wq_b^T   [2048,4096], K=1024
    gemm_bfs<<<dim3(16, 32, 1), blk, GBF_SMEM>>>(qah, qal, QL_, wqbh, wqbl, QL_,
                                                 qbuf, H_ * D_, QL_, 0, 0, 0);
    // kv: rms + rope -> bf16 hi/lo (warp-per-row)
    kvprep<<<S_ / 8, 256>>>(kvbuf, kv_norm_w, freqs, kvh, kvl);
    // q: head-norm + rope + scale -> bf16 hi/lo (warp-per-row)
    qprep<<<S_ * H_ / 8, 256>>>(qbuf, freqs, qhh, qll);
    // attention (WMMA, 64q tiles, KV double-buffered) -> o hi/lo with fused conj-RoPE
    attn_wmma<<<dim3(S_ / 64, H_), blk, ATT_SMEM>>>(qhh, qll, kvh, kvl,
                                                    attn_sink, freqs, oh, ol);
    // grouped low-rank: z = 4 groups, [2048,512] each, K=1024
    gemm_bfs<<<dim3(16, 4, 4), blk, GBF_SMEM>>>(oh, ol, H_ * D_, woah, woal, 1024,
                                                orbuf, G_ * OR_, 1024,
                                                1024L, (long)OR_ * 1024L, (long)OR_);
    // o_r -> hi/lo
    cvt_hilo<<<(S_*G_*OR_/4 + 255)/256, 256>>>(orbuf, orh, orl, S_*G_*OR_/4);
    // out = o_r @ wo_b^T [2048,2048], K=2048
    gemm_bfs<<<dim3(16, 16, 1), blk, GBF_SMEM>>>(orh, orl, G_ * OR_, wobh, wobl, HID_,
                                                 out, HID_, G_ * OR_, 0, 0, 0);
}

// round 17
// speedup vs baseline: 1.0200x; 1.0200x over previous
#include <cuda_runtime.h>
#include <cuda_bf16.h>
#include <mma.h>
#include <math.h>
#include <stdint.h>

using namespace nvcuda;

#define S_    2048
#define HID_  2048
#define H_    16
#define D_    256
#define NOPE_ 192
#define RH_   32
#define QL_   1024
#define OR_   512
#define G_    4
#define EPS_  1e-6f
#define SCALE_ 0.0625f

// -------- fp32 scratch --------
__device__ float g_qa[S_ * QL_];
__device__ float g_q[(size_t)S_ * H_ * D_];
__device__ float g_kv[S_ * D_];
__device__ float g_or[S_ * G_ * OR_];

// -------- bf16 hi/lo scratch --------
__device__ __nv_bfloat16 g_xh[S_ * HID_],        g_xl[S_ * HID_];
__device__ __nv_bfloat16 g_wqah[QL_ * HID_],     g_wqal[QL_ * HID_];
__device__ __nv_bfloat16 g_wqbh[H_ * D_ * QL_],  g_wqbl[H_ * D_ * QL_];
__device__ __nv_bfloat16 g_qah[S_ * QL_],        g_qal[S_ * QL_];
__device__ __nv_bfloat16 g_wkvh[D_ * HID_],      g_wkvl[D_ * HID_];
__device__ __nv_bfloat16 g_woah[G_ * OR_ * 1024], g_woal[G_ * OR_ * 1024];
__device__ __nv_bfloat16 g_wobh[HID_ * G_ * OR_], g_wobl[HID_ * G_ * OR_];
__device__ __nv_bfloat16 g_oh[(size_t)S_ * H_ * D_], g_ol[(size_t)S_ * H_ * D_];
__device__ __nv_bfloat16 g_orh[S_ * G_ * OR_],   g_orl[S_ * G_ * OR_];
// attention bf16 operands
__device__ __nv_bfloat16 g_qh[(size_t)S_ * H_ * D_], g_ql2[(size_t)S_ * H_ * D_];
__device__ __nv_bfloat16 g_kvh[S_ * D_],         g_kvl[S_ * D_];

__device__ __forceinline__ uint32_t b2u(__nv_bfloat162 h) {
    return *reinterpret_cast<uint32_t*>(&h);
}
__device__ __forceinline__ void cp16(void* smem_dst, const void* gsrc) {
    uint32_t s = (uint32_t)__cvta_generic_to_shared(smem_dst);
    asm volatile("cp.async.cg.shared.global [%0], [%1], 16;" :: "r"(s), "l"(gsrc) : "memory");
}
#define CP_COMMIT() asm volatile("cp.async.commit_group;" ::: "memory")
#define CP_WAIT0()  asm volatile("cp.async.wait_group 0;" ::: "memory")

// ==================== fp32 -> (hi, lo) bf16 conversion ====================
__global__ void cvt_hilo(const float* __restrict__ in,
                         __nv_bfloat16* __restrict__ h,
                         __nv_bfloat16* __restrict__ l, int n4)
{
    int i = blockIdx.x * blockDim.x + threadIdx.x;
    if (i >= n4) return;
    float4 v = ((const float4*)in)[i];
    __nv_bfloat162 h01 = __floats2bfloat162_rn(v.x, v.y);
    __nv_bfloat162 h23 = __floats2bfloat162_rn(v.z, v.w);
    __nv_bfloat162 l01 = __floats2bfloat162_rn(
        v.x - __bfloat162float(__low2bfloat16(h01)),
        v.y - __bfloat162float(__high2bfloat16(h01)));
    __nv_bfloat162 l23 = __floats2bfloat162_rn(
        v.z - __bfloat162float(__low2bfloat16(h23)),
        v.w - __bfloat162float(__high2bfloat16(h23)));
    ((uint2*)h)[i] = make_uint2(b2u(h01), b2u(h23));
    ((uint2*)l)[i] = make_uint2(b2u(l01), b2u(l23));
}

// ==================== split-bf16 tensor GEMM (R15 proven shape: 2 CTAs/SM) ====================
#define BST 72
#define GBF_SMEM (4 * 128 * BST * 2)

__global__ void __launch_bounds__(256, 2) gemm_bfs(
    const __nv_bfloat16* __restrict__ Ah, const __nv_bfloat16* __restrict__ Al, int lda,
    const __nv_bfloat16* __restrict__ Bh, const __nv_bfloat16* __restrict__ Bl, int ldb,
    float* __restrict__ C, int ldc, int K,
    long sAz, long sBz, long sCz)
{
    extern __shared__ __nv_bfloat16 sb[];
    __nv_bfloat16* Ah_s = sb;
    __nv_bfloat16* Al_s = sb + 128 * BST;
    __nv_bfloat16* Bh_s = sb + 2 * 128 * BST;
    __nv_bfloat16* Bl_s = sb + 3 * 128 * BST;

    Ah += (size_t)blockIdx.z * sAz;  Al += (size_t)blockIdx.z * sAz;
    Bh += (size_t)blockIdx.z * sBz;  Bl += (size_t)blockIdx.z * sBz;
    C  += (size_t)blockIdx.z * sCz;

    const int tid = threadIdx.x;
    const int warp = tid >> 5;
    const int wm = warp & 1, wn = warp >> 1;

    wmma::fragment<wmma::accumulator, 16, 16, 16, float> acc[4][2];
    #pragma unroll
    for (int i = 0; i < 4; i++)
        #pragma unroll
        for (int j = 0; j < 2; j++)
            wmma::fill_fragment(acc[i][j], 0.0f);

    const int r  = tid >> 1;
    const int c0 = (tid & 1) * 32;
    const size_t aoff = (size_t)(blockIdx.x * 128 + r) * lda + c0;
    const size_t boff = (size_t)(blockIdx.y * 128 + r) * ldb + c0;
    const int sidx = r * BST + c0;

    const int nkc = K >> 6;
    for (int kc = 0; kc < nkc; kc++) {
        __syncthreads();
        {
            const uint4* gah = (const uint4*)(Ah + aoff + kc * 64);
            const uint4* gal = (const uint4*)(Al + aoff + kc * 64);
            const uint4* gbh = (const uint4*)(Bh + boff + kc * 64);
            const uint4* gbl = (const uint4*)(Bl + boff + kc * 64);
            #pragma unroll
            for (int j = 0; j < 4; j++) {
                *(uint4*)(Ah_s + sidx + j * 8) = gah[j];
                *(uint4*)(Al_s + sidx + j * 8) = gal[j];
                *(uint4*)(Bh_s + sidx + j * 8) = gbh[j];
                *(uint4*)(Bl_s + sidx + j * 8) = gbl[j];
            }
        }
        __syncthreads();

        #pragma unroll
        for (int ks = 0; ks < 4; ks++) {
            wmma::fragment<wmma::matrix_a, 16, 16, 16, __nv_bfloat16, wmma::row_major> ah[4];
            wmma::fragment<wmma::matrix_b, 16, 16, 16, __nv_bfloat16, wmma::col_major> bh[2];
            #pragma unroll
            for (int i = 0; i < 4; i++)
                wmma::load_matrix_sync(ah[i], Ah_s + (wm * 64 + i * 16) * BST + ks * 16, BST);
            #pragma unroll
            for (int j = 0; j < 2; j++)
                wmma::load_matrix_sync(bh[j], Bh_s + (wn * 32 + j * 16) * BST + ks * 16, BST);
            #pragma unroll
            for (int i = 0; i < 4; i++)
                #pragma unroll
                for (int j = 0; j < 2; j++)
                    wmma::mma_sync(acc[i][j], ah[i], bh[j], acc[i][j]);
            {
                wmma::fragment<wmma::matrix_b, 16, 16, 16, __nv_bfloat16, wmma::col_major> bl[2];
                #pragma unroll
                for (int j = 0; j < 2; j++)
                    wmma::load_matrix_sync(bl[j], Bl_s + (wn * 32 + j * 16) * BST + ks * 16, BST);
                #pragma unroll
                for (int i = 0; i < 4; i++)
                    #pragma unroll
                    for (int j = 0; j < 2; j++)
                        wmma::mma_sync(acc[i][j], ah[i], bl[j], acc[i][j]);
            }
            {
                wmma::fragment<wmma::matrix_a, 16, 16, 16, __nv_bfloat16, wmma::row_major> al[4];
                #pragma unroll
                for (int i = 0; i < 4; i++)
                    wmma::load_matrix_sync(al[i], Al_s + (wm * 64 + i * 16) * BST + ks * 16, BST);
                #pragma unroll
                for (int i = 0; i < 4; i++)
                    #pragma unroll
                    for (int j = 0; j < 2; j++)
                        wmma::mma_sync(acc[i][j], al[i], bh[j], acc[i][j]);
            }
        }
    }

    #pragma unroll
    for (int i = 0; i < 4; i++)
        #pragma unroll
        for (int j = 0; j < 2; j++) {
            float* Cp = C + (size_t)(blockIdx.x * 128 + wm * 64 + i * 16) * ldc
                          + blockIdx.y * 128 + wn * 32 + j * 16;
            wmma::store_matrix_sync(Cp, acc[i][j], ldc, wmma::mem_row_major);
        }
}

// ==================== RMS norm (L=1024) emitting hi/lo bf16 ====================
__global__ void rmsnorm_hilo(const float* __restrict__ x, const float* __restrict__ w,
                             __nv_bfloat16* __restrict__ h, __nv_bfloat16* __restrict__ l)
{
    int row = blockIdx.x;
    int t = threadIdx.x;
    const float4* p = (const float4*)(x + (size_t)row * QL_);
    float4 v = p[t];
    float ss = v.x * v.x + v.y * v.y + v.z * v.z + v.w * v.w;
    __shared__ float red[8];
    #pragma unroll
    for (int o = 16; o; o >>= 1) ss += __shfl_xor_sync(0xffffffffu, ss, o);
    if ((t & 31) == 0) red[t >> 5] = ss;
    __syncthreads();
    if (t < 32) {
        float r = (t < 8) ? red[t] : 0.f;
        #pragma unroll
        for (int o = 4; o; o >>= 1) r += __shfl_xor_sync(0xffffffffu, r, o);
        if (t == 0) red[0] = r;
    }
    __syncthreads();
    float inv = rsqrtf(red[0] / (float)QL_ + EPS_);
    float4 wv = ((const float4*)w)[t];
    float4 o4 = make_float4(v.x * inv * wv.x, v.y * inv * wv.y,
                            v.z * inv * wv.z, v.w * inv * wv.w);
    __nv_bfloat162 h01 = __floats2bfloat162_rn(o4.x, o4.y);
    __nv_bfloat162 h23 = __floats2bfloat162_rn(o4.z, o4.w);
    __nv_bfloat162 l01 = __floats2bfloat162_rn(
        o4.x - __bfloat162float(__low2bfloat16(h01)),
        o4.y - __bfloat162float(__high2bfloat16(h01)));
    __nv_bfloat162 l23 = __floats2bfloat162_rn(
        o4.z - __bfloat162float(__low2bfloat16(h23)),
        o4.w - __bfloat162float(__high2bfloat16(h23)));
    ((uint2*)(h + (size_t)row * QL_))[t] = make_uint2(b2u(h01), b2u(h23));
    ((uint2*)(l + (size_t)row * QL_))[t] = make_uint2(b2u(l01), b2u(l23));
}

// ==================== q prep: warp-per-row ====================
__global__ void qprep(const float* __restrict__ q, const float* __restrict__ freqs,
                      __nv_bfloat16* __restrict__ qh, __nv_bfloat16* __restrict__ ql)
{
    int row = blockIdx.x * 8 + (threadIdx.x >> 5);
    int lane = threadIdx.x & 31;
    const float* p = q + (size_t)row * D_ + lane * 8;
    float4 a = *(const float4*)p;
    float4 b = *(const float4*)(p + 4);
    float ss = a.x*a.x + a.y*a.y + a.z*a.z + a.w*a.w
             + b.x*b.x + b.y*b.y + b.z*b.z + b.w*b.w;
    #pragma unroll
    for (int o = 16; o; o >>= 1) ss += __shfl_xor_sync(0xffffffffu, ss, o);
    float inv = rsqrtf(ss / (float)D_ + EPS_) * SCALE_;
    float v[8] = {a.x*inv, a.y*inv, a.z*inv, a.w*inv,
                  b.x*inv, b.y*inv, b.z*inv, b.w*inv};
    int col0 = lane * 8;
    if (col0 >= NOPE_) {
        int s = row >> 4;
        #pragma unroll
        for (int j = 0; j < 8; j += 2) {
            int i = (col0 + j - NOPE_) >> 1;
            float f = freqs[s * RH_ + i];
            float c = cosf(f), sn = sinf(f);
            float x1 = v[j], x2 = v[j + 1];
            v[j]     = x1 * c - x2 * sn;
            v[j + 1] = x1 * sn + x2 * c;
        }
    }
    uint32_t hh[4], ll[4];
    #pragma unroll
    for (int j = 0; j < 4; j++) {
        __nv_bfloat162 hi = __floats2bfloat162_rn(v[2*j], v[2*j+1]);
        __nv_bfloat162 lo = __floats2bfloat162_rn(
            v[2*j]   - __bfloat162float(__low2bfloat16(hi)),
            v[2*j+1] - __bfloat162float(__high2bfloat16(hi)));
        hh[j] = b2u(hi); ll[j] = b2u(lo);
    }
    size_t idx = (size_t)row * D_ + col0;
    *(uint4*)(qh + idx) = make_uint4(hh[0], hh[1], hh[2], hh[3]);
    *(uint4*)(ql + idx) = make_uint4(ll[0], ll[1], ll[2], ll[3]);
}

// ==================== kv prep: warp-per-row ====================
__global__ void kvprep(const float* __restrict__ kv, const float* __restrict__ w,
                       const float* __restrict__ freqs,
                       __nv_bfloat16* __restrict__ kvh, __nv_bfloat16* __restrict__ kvl)
{
    int s = blockIdx.x * 8 + (threadIdx.x >> 5);
    int lane = threadIdx.x & 31;
    const float* p = kv + (size_t)s * D_ + lane * 8;
    float4 a = *(const float4*)p;
    float4 b = *(const float4*)(p + 4);
    float ss = a.x*a.x + a.y*a.y + a.z*a.z + a.w*a.w
             + b.x*b.x + b.y*b.y + b.z*b.z + b.w*b.w;
    #pragma unroll
    for (int o = 16; o; o >>= 1) ss += __shfl_xor_sync(0xffffffffu, ss, o);
    float inv = rsqrtf(ss / (float)D_ + EPS_);
    float4 w0 = *(const float4*)(w + lane * 8);
    float4 w1 = *(const float4*)(w + lane * 8 + 4);
    float v[8] = {a.x*inv*w0.x, a.y*inv*w0.y, a.z*inv*w0.z, a.w*inv*w0.w,
                  b.x*inv*w1.x, b.y*inv*w1.y, b.z*inv*w1.z, b.w*inv*w1.w};
    int col0 = lane * 8;
    if (col0 >= NOPE_) {
        #pragma unroll
        for (int j = 0; j < 8; j += 2) {
            int i = (col0 + j - NOPE_) >> 1;
            float f = freqs[s * RH_ + i];
            float c = cosf(f), sn = sinf(f);
            float x1 = v[j], x2 = v[j + 1];
            v[j]     = x1 * c - x2 * sn;
            v[j + 1] = x1 * sn + x2 * c;
        }
    }
    uint32_t hh[4], ll[4];
    #pragma unroll
    for (int j = 0; j < 4; j++) {
        __nv_bfloat162 hi = __floats2bfloat162_rn(v[2*j], v[2*j+1]);
        __nv_bfloat162 lo = __floats2bfloat162_rn(
            v[2*j]   - __bfloat162float(__low2bfloat16(hi)),
            v[2*j+1] - __bfloat162float(__high2bfloat16(hi)));
        hh[j] = b2u(hi); ll[j] = b2u(lo);
    }
    size_t idx = (size_t)s * D_ + col0;
    *(uint4*)(kvh + idx) = make_uint4(hh[0], hh[1], hh[2], hh[3]);
    *(uint4*)(kvl + idx) = make_uint4(ll[0], ll[1], ll[2], ll[3]);
}

// ==================== WMMA flash attention, 64q x 64k, KV double-buffered (cp.async) ========
#define AQS 264
#define APS 72
#define PVS 260
#define ATT_SMEM (2*64*AQS*2 + 4*64*AQS*2 + 64*APS*4 + 64*4)

__global__ void __launch_bounds__(256) attn_wmma(
    const __nv_bfloat16* __restrict__ qh, const __nv_bfloat16* __restrict__ ql,
    const __nv_bfloat16* __restrict__ kvh, const __nv_bfloat16* __restrict__ kvl,
    const float* __restrict__ sink, const float* __restrict__ freqs,
    __nv_bfloat16* __restrict__ ohi, __nv_bfloat16* __restrict__ olo)
{
    extern __shared__ char sm8[];
    __nv_bfloat16* Qh  = (__nv_bfloat16*)sm8;
    __nv_bfloat16* Ql  = Qh + 64 * AQS;
    __nv_bfloat16* KVbase = Ql + 64 * AQS;
    float* Sf = (float*)(KVbase + 4 * 64 * AQS);
    __nv_bfloat16* Ph = (__nv_bfloat16*)Sf;
    __nv_bfloat16* Pl = Ph + 64 * APS;
    float* rowl = Sf + 64 * APS;
    float* PVb = (float*)Qh;

    const int qb = (int)(gridDim.x - 1 - blockIdx.x);
    const int h  = blockIdx.y;
    const int s0 = qb * 64;
    const int tid = threadIdx.x;
    const int warp = tid >> 5;

    const int kr = tid >> 2, kc0 = (tid & 3) * 64;

    {
        __nv_bfloat16* KVh0 = KVbase;
        __nv_bfloat16* KVl0 = KVbase + 64 * AQS;
        const __nv_bfloat16* gh = kvh + (size_t)kr * D_ + kc0;
        const __nv_bfloat16* gl = kvl + (size_t)kr * D_ + kc0;
        #pragma unroll
        for (int j = 0; j < 8; j++) {
            cp16(KVh0 + kr * AQS + kc0 + j * 8, gh + j * 8);
            cp16(KVl0 + kr * AQS + kc0 + j * 8, gl + j * 8);
        }
        CP_COMMIT();
    }

    {
        int r = tid >> 2, c0 = (tid & 3) * 64;
        const uint4* gh = (const uint4*)(qh + ((size_t)(s0 + r) * H_ + h) * D_ + c0);
        const uint4* gl = (const uint4*)(ql + ((size_t)(s0 + r) * H_ + h) * D_ + c0);
        #pragma unroll
        for (int j = 0; j < 8; j++) {
            *(uint4*)(Qh + r * AQS + c0 + j * 8) = gh[j];
            *(uint4*)(Ql + r * AQS + c0 + j * 8) = gl[j];
        }
    }
    if (tid < 64) rowl[tid] = 0.f;

    const int wS_m = warp & 3, wS_n = warp >> 2;
    const int wP_m = warp & 1, wP_n = warp >> 1;

    wmma::fragment<wmma::accumulator, 16, 16, 16, float> pacc[2][4];
    #pragma unroll
    for (int i = 0; i < 2; i++)
        #pragma unroll
        for (int n = 0; n < 4; n++) wmma::fill_fragment(pacc[i][n], 0.0f);

    CP_WAIT0();
    __syncthreads();

    const int ntiles = qb + 1;
    for (int t0 = 0; t0 < ntiles; t0++) {
        const int cur = t0 & 1;
        __nv_bfloat16* KVh = KVbase + cur * (2 * 64 * AQS);
        __nv_bfloat16* KVl = KVh + 64 * AQS;

        if (t0 + 1 < ntiles) {
            __nv_bfloat16* KVhN = KVbase + (cur ^ 1) * (2 * 64 * AQS);
            __nv_bfloat16* KVlN = KVhN + 64 * AQS;
            const __nv_bfloat16* gh = kvh + (size_t)((t0 + 1) * 64 + kr) * D_ + kc0;
            const __nv_bfloat16* gl = kvl + (size_t)((t0 + 1) * 64 + kr) * D_ + kc0;
            #pragma unroll
            for (int j = 0; j < 8; j++) {
                cp16(KVhN + kr * AQS + kc0 + j * 8, gh + j * 8);
                cp16(KVlN + kr * AQS + kc0 + j * 8, gl + j * 8);
            }
            CP_COMMIT();
        }

        {
            wmma::fragment<wmma::accumulator, 16, 16, 16, float> sacc[2];
            #pragma unroll
            for (int j = 0; j < 2; j++) wmma::fill_fragment(sacc[j], 0.0f);
            #pragma unroll 2
            for (int ks = 0; ks < 16; ks++) {
                wmma::fragment<wmma::matrix_a, 16, 16, 16, __nv_bfloat16, wmma::row_major> ah, al;
                wmma::fragment<wmma::matrix_b, 16, 16, 16, __nv_bfloat16, wmma::col_major> bh[2], bl[2];
                wmma::load_matrix_sync(ah, Qh + (wS_m * 16) * AQS + ks * 16, AQS);
                wmma::load_matrix_sync(al, Ql + (wS_m * 16) * AQS + ks * 16, AQS);
                #pragma unroll
                for (int j = 0; j < 2; j++) {
                    wmma::load_matrix_sync(bh[j], KVh + (wS_n * 32 + j * 16) * AQS + ks * 16, AQS);
                    wmma::load_matrix_sync(bl[j], KVl + (wS_n * 32 + j * 16) * AQS + ks * 16, AQS);
                }
                #pragma unroll
                for (int j = 0; j < 2; j++) {
                    wmma::mma_sync(sacc[j], ah, bh[j], sacc[j]);
                    wmma::mma_sync(sacc[j], ah, bl[j], sacc[j]);
                    wmma::mma_sync(sacc[j], al, bh[j], sacc[j]);
                }
            }
            #pragma unroll
            for (int j = 0; j < 2; j++)
                wmma::store_matrix_sync(Sf + (wS_m * 16) * APS + wS_n * 32 + j * 16,
                                        sacc[j], APS, wmma::mem_row_major);
        }
        __syncthreads();

        {
            int r = tid >> 2, sub = tid & 3;
            float e[16];
            float psum = 0.f;
            #pragma unroll
            for (int tt = 0; tt < 16; tt++) {
                int c = sub * 16 + tt;
                float v = Sf[r * APS + c];
                e[tt] = (t0 * 64 + c <= s0 + r) ? __expf(v) : 0.f;
                psum += e[tt];
            }
            psum += __shfl_xor_sync(0xffffffffu, psum, 1);
            psum += __shfl_xor_sync(0xffffffffu, psum, 2);
            if (sub == 0) rowl[r] += psum;
            __syncthreads();
            #pragma unroll
            for (int tt = 0; tt < 16; tt++) {
                int c = sub * 16 + tt;
                __nv_bfloat16 hi = __float2bfloat16(e[tt]);
                Ph[r * APS + c] = hi;
                Pl[r * APS + c] = __float2bfloat16(e[tt] - __bfloat162float(hi));
            }
        }
        __syncthreads();

        #pragma unroll
        for (int ks = 0; ks < 4; ks++) {
            wmma::fragment<wmma::matrix_a, 16, 16, 16, __nv_bfloat16, wmma::row_major> ph[2], pl[2];
            #pragma unroll
            for (int i = 0; i < 2; i++) {
                wmma::load_matrix_sync(ph[i], Ph + (wP_m * 32 + i * 16) * APS + ks * 16, APS);
                wmma::load_matrix_sync(pl[i], Pl + (wP_m * 32 + i * 16) * APS + ks * 16, APS);
            }
            #pragma unroll
            for (int n = 0; n < 4; n++) {
                wmma::fragment<wmma::matrix_b, 16, 16, 16, __nv_bfloat16, wmma::row_major> bh, bl;
                wmma::load_matrix_sync(bh, KVh + (ks * 16) * AQS + wP_n * 64 + n * 16, AQS);
                wmma::load_matrix_sync(bl, KVl + (ks * 16) * AQS + wP_n * 64 + n * 16, AQS);
                #pragma unroll
                for (int i = 0; i < 2; i++) {
                    wmma::mma_sync(pacc[i][n], ph[i], bh, pacc[i][n]);
                    wmma::mma_sync(pacc[i][n], ph[i], bl, pacc[i][n]);
                    wmma::mma_sync(pacc[i][n], pl[i], bh, pacc[i][n]);
                }
            }
        }
        CP_WAIT0();
        __syncthreads();
    }

    #pragma unroll
    for (int i = 0; i < 2; i++)
        #pragma unroll
        for (int n = 0; n < 4; n++)
            wmma::store_matrix_sync(PVb + (wP_m * 32 + i * 16) * PVS + wP_n * 64 + n * 16,
                                    pacc[i][n], PVS, wmma::mem_row_major);
    __syncthreads();

    const int ty = tid >> 4, tx = tid & 15;
    float sk = __expf(sink[h]);
    #pragma unroll
    for (int i = 0; i < 4; i++) {
        int r = ty * 4 + i;
        int s = s0 + r;
        float inv = 1.f / (rowl[r] + sk);
        #pragma unroll
        for (int g = 0; g < 4; g++) {
            float4 pv = *(const float4*)&PVb[r * PVS + tx * 4 + g * 64];
            float4 v = make_float4(pv.x * inv, pv.y * inv, pv.z * inv, pv.w * inv);
            if (g == 3) {
                float f0 = freqs[s * RH_ + tx * 2];
                float f1 = freqs[s * RH_ + tx * 2 + 1];
                float c0 = cosf(f0), sn0 = sinf(f0);
                float c1 = cosf(f1), sn1 = sinf(f1);
                float x1 = v.x, x2 = v.y;
                v.x = x1 * c0 + x2 * sn0;
                v.y = x2 * c0 - x1 * sn0;
                float y1 = v.z, y2 = v.w;
                v.z = y1 * c1 + y2 * sn1;
                v.w = y2 * c1 - y1 * sn1;
            }
            __nv_bfloat162 h01 = __floats2bfloat162_rn(v.x, v.y);
            __nv_bfloat162 h23 = __floats2bfloat162_rn(v.z, v.w);
            __nv_bfloat162 l01 = __floats2bfloat162_rn(
                v.x - __bfloat162float(__low2bfloat16(h01)),
                v.y - __bfloat162float(__high2bfloat16(h01)));
            __nv_bfloat162 l23 = __floats2bfloat162_rn(
                v.z - __bfloat162float(__low2bfloat16(h23)),
                v.w - __bfloat162float(__high2bfloat16(h23)));
            size_t oidx = ((size_t)s * H_ + h) * D_ + tx * 4 + g * 64;
            *(uint2*)(ohi + oidx) = make_uint2(b2u(h01), b2u(h23));
            *(uint2*)(olo + oidx) = make_uint2(b2u(l01), b2u(l23));
        }
    }
}

// ==================== launch ====================
extern "C" void kernel_launch(void* const* d_in, const int* in_sizes, int n_in,
                              void* d_out, int out_size)
{
    const float* x         = (const float*)d_in[0];
    const float* freqs     = (const float*)d_in[1];
    const float* wq_a      = (const float*)d_in[2];
    const float* q_norm_w  = (const float*)d_in[3];
    const float* wq_b      = (const float*)d_in[4];
    const float* wkv       = (const float*)d_in[5];
    const float* kv_norm_w = (const float*)d_in[6];
    const float* wo_a_w    = (const float*)d_in[7];
    const float* wo_b      = (const float*)d_in[8];
    const float* attn_sink = (const float*)d_in[9];
    float* out = (float*)d_out;

    float *qa, *qbuf, *kvbuf, *orbuf;
    cudaGetSymbolAddress((void**)&qa,    g_qa);
    cudaGetSymbolAddress((void**)&qbuf,  g_q);
    cudaGetSymbolAddress((void**)&kvbuf, g_kv);
    cudaGetSymbolAddress((void**)&orbuf, g_or);

    __nv_bfloat16 *xh, *xl, *wqah, *wqal, *wqbh, *wqbl, *qah, *qal;
    __nv_bfloat16 *wkvh, *wkvl, *woah, *woal, *wobh, *wobl, *oh, *ol, *orh, *orl;
    __nv_bfloat16 *qhh, *qll, *kvh, *kvl;
    cudaGetSymbolAddress((void**)&xh, g_xh);     cudaGetSymbolAddress((void**)&xl, g_xl);
    cudaGetSymbolAddress((void**)&wqah, g_wqah); cudaGetSymbolAddress((void**)&wqal, g_wqal);
    cudaGetSymbolAddress((void**)&wqbh, g_wqbh); cudaGetSymbolAddress((void**)&wqbl, g_wqbl);
    cudaGetSymbolAddress((void**)&qah, g_qah);   cudaGetSymbolAddress((void**)&qal, g_qal);
    cudaGetSymbolAddress((void**)&wkvh, g_wkvh); cudaGetSymbolAddress((void**)&wkvl, g_wkvl);
    cudaGetSymbolAddress((void**)&woah, g_woah); cudaGetSymbolAddress((void**)&woal, g_woal);
    cudaGetSymbolAddress((void**)&wobh, g_wobh); cudaGetSymbolAddress((void**)&wobl, g_wobl);
    cudaGetSymbolAddress((void**)&oh, g_oh);     cudaGetSymbolAddress((void**)&ol, g_ol);
    cudaGetSymbolAddress((void**)&orh, g_orh);   cudaGetSymbolAddress((void**)&orl, g_orl);
    cudaGetSymbolAddress((void**)&qhh, g_qh);    cudaGetSymbolAddress((void**)&qll, g_ql2);
    cudaGetSymbolAddress((void**)&kvh, g_kvh);   cudaGetSymbolAddress((void**)&kvl, g_kvl);

    static int smem_set = 0;
    if (!smem_set) {
        cudaFuncSetAttribute(attn_wmma, cudaFuncAttributeMaxDynamicSharedMemorySize,
                             ATT_SMEM);
        cudaFuncSetAttribute(gemm_bfs, cudaFuncAttributeMaxDynamicSharedMemorySize,
                             GBF_SMEM);
        smem_set = 1;
    }

    dim3 blk(256);
    // ---- conversions (inputs + weights) ----
    cvt_hilo<<<(S_*HID_/4 + 255)/256, 256>>>(x,      xh,   xl,   S_*HID_/4);
    cvt_hilo<<<(QL_*HID_/4 + 255)/256, 256>>>(wq_a,  wqah, wqal, QL_*HID_/4);
    cvt_hilo<<<(H_*D_*QL_/4 + 255)/256, 256>>>(wq_b, wqbh, wqbl, H_*D_*QL_/4);
    cvt_hilo<<<(D_*HID_/4 + 255)/256, 256>>>(wkv,    wkvh, wkvl, D_*HID_/4);
    cvt_hilo<<<(G_*OR_*1024/4 + 255)/256, 256>>>(wo_a_w, woah, woal, G_*OR_*1024/4);
    cvt_hilo<<<(HID_*G_*OR_/4 + 255)/256, 256>>>(wo_b, wobh, wobl, HID_*G_*OR_/4);

    // q_a = x @ wq_a^T   [2048,1024], K=2048
    gemm_bfs<<<dim3(16, 8, 1), blk, GBF_SMEM>>>(xh, xl, HID_, wqah, wqal, HID_,
                                                qa, QL_, HID_, 0, 0, 0);
    // kv_raw = x @ wkv^T [2048,256], K=2048 (tensor path)
    gemm_bfs<<<dim3(16, 2, 1), blk, GBF_SMEM>>>(xh, xl, HID_, wkvh, wkvl, HID_,
                                                kvbuf, D_, HID_, 0, 0, 0);
    // rms(q_a) -> hi/lo
    rmsnorm_hilo<<<S_, 256>>>(qa, q_norm_w, qah, qal);
    // q = q_a @ wq_b^T   [2048,4096], K=1024
    gemm_bfs<<<dim3(16, 32, 1), blk, GBF_SMEM>>>(qah, qal, QL_, wqbh, wqbl, QL_,
                                                 qbuf, H_ * D_, QL_, 0, 0, 0);
    // kv: rms + rope -> bf16 hi/lo (warp-per-row)
    kvprep<<<S_ / 8, 256>>>(kvbuf, kv_norm_w, freqs, kvh, kvl);
    // q: head-norm + rope + scale -> bf16 hi/lo (warp-per-row)
    qprep<<<S_ * H_ / 8, 256>>>(qbuf, freqs, qhh, qll);
    // attention (WMMA, 64q tiles, KV double-buffered) -> o hi/lo with fused conj-RoPE
    attn_wmma<<<dim3(S_ / 64, H_), blk, ATT_SMEM>>>(qhh, qll, kvh, kvl,
                                                    attn_sink, freqs, oh, ol);
    // grouped low-rank: z = 4 groups, [2048,512] each, K=1024
    gemm_bfs<<<dim3(16, 4, 4), blk, GBF_SMEM>>>(oh, ol, H_ * D_, woah, woal, 1024,
                                                orbuf, G_ * OR_, 1024,
                                                1024L, (long)OR_ * 1024L, (long)OR_);
    // o_r -> hi/lo
    cvt_hilo<<<(S_*G_*OR_/4 + 255)/256, 256>>>(orbuf, orh, orl, S_*G_*OR_/4);
    // out = o_r @ wo_b^T [2048,2048], K=2048
    gemm_bfs<<<dim3(16, 16, 1), blk, GBF_SMEM>>>(orh, orl, G_ * OR_, wobh, wobl, HID_,
                                                 out, HID_, G_ * OR_, 0, 0, 0);
}